// round 16
// baseline (speedup 1.0000x reference)
#include <cuda_runtime.h>
#include <math.h>

// Problem constants (fixed by the reference's setup_inputs)
#define NROWS   8192           // B
#define SLEN    4096           // S
#define WARPS   8              // warps per block; block owns one row
#define BLOCK   (WARPS * 32)   // 256 threads
#define RSTEPS  (WARPS * 128)  // 1024 steps per round (16 KB contiguous)
#define NR      (SLEN / RSTEPS) // 4 rounds per row

#define DELTA_T 900.0
// COOLING_SIGN = -1.0

__device__ __forceinline__ double bounded_d(double raw, double lo, double hi) {
    double s = 1.0 / (1.0 + exp(-raw));
    return lo + (hi - lo) * s;
}

// Cooperative block-per-row scan. t' = a*t + b_s, constant a.
// R15 post-mortem: HBM clamps ~4.7TB/s for ~5500 concurrent per-warp read
// streams regardless of MLP/shuffles/TMA => DRAM row-locality limit. Here ONE
// block (8 warps) owns a row: per round it reads 16KB contiguous, each warp
// runs the R13-validated 128-step blocked K=4 scan on its 2KB segment, and an
// 8-entry smem carry combine links warps (1 syncthreads/round, 4 rounds).
// Concurrent streams: 5500 -> ~590, each wide and sequential.
__global__ __launch_bounds__(BLOCK)
void rc_scan_kernel(const float4* __restrict__ in,
                    const float*  __restrict__ pR,
                    const float*  __restrict__ pC,
                    const float*  __restrict__ pA,
                    const float*  __restrict__ pG,
                    float*        __restrict__ out)
{
    __shared__ __align__(16) float sb[WARPS][2][128];  // b transpose, per warp
    __shared__ float warpS[2][WARPS];                  // warp totals (scaled)

    const int wid  = threadIdx.x >> 5;     // warp id in block (0..7)
    const int lane = threadIdx.x & 31;
    const int row  = blockIdx.x;           // one row per block

    // --- scalar parameters (sigmoid-bounded), computed in double, negligible ---
    const double R = bounded_d((double)*pR, 1e-4, 0.2);
    const double C = bounded_d((double)*pC, 1e5, 1e8);
    const double A = bounded_d((double)*pA, 0.0, 0.2);
    const double G = bounded_d((double)*pG, 1.0, 20000.0);

    const double dtC = DELTA_T / C;
    const double a_d = 1.0 - dtC / R;       // ~0.9633 for given inputs
    const float  a   = (float)a_d;
    const float  kTo = (float)(dtC / R);    // coeff of t_out
    const float  kU  = (float)(-G * dtC);   // COOLING_SIGN * g * dt/C
    const float  kSo = (float)(A * dtC);    // coeff of solar

    const double la = log(a_d);
    const float ap4l   = (float)exp( la * (4.0 * lane));        // a^{4l}
    const float ainv4l = (float)exp(-la * (4.0 * lane));        // a^{-4l}
    const float ap4lm4 = (float)exp( la * (4.0 * lane - 4.0));  // a^{4l-4}
    const float a128   = (float)exp( la * 128.0);               // a^128
    const float a124   = (float)exp( la * 124.0);               // a^124

    const float4* rowp  = in + (size_t)row * SLEN;   // 16 B per step
    float4*       orow4 = (float4*)(out + (size_t)row * SLEN);

    // initial carry = t_in[row, 0] (channel x of step 0); broadcast load
    float t = __ldg((const float*)rowp);

    // prefetch round 0: warp wid's 128-step segment, 4 coalesced float4 loads
    const float4* seg0 = rowp + wid * 128;
    float4 v0 = seg0[      lane];
    float4 v1 = seg0[ 32 + lane];
    float4 v2 = seg0[ 64 + lane];
    float4 v3 = seg0[ 96 + lane];

    #pragma unroll
    for (int r = 0; r < NR; r++) {
        // forcing terms for the 4 owned (strided) steps
        float b0 = fmaf(kTo, v0.y, fmaf(kU, v0.z, kSo * v0.w));
        float b1 = fmaf(kTo, v1.y, fmaf(kU, v1.z, kSo * v1.w));
        float b2 = fmaf(kTo, v2.y, fmaf(kU, v2.z, kSo * v2.w));
        float b3 = fmaf(kTo, v3.y, fmaf(kU, v3.z, kSo * v3.w));

        // prefetch next round's segment (in flight across the barrier)
        if (r + 1 < NR) {
            const float4* seg = rowp + (r + 1) * (RSTEPS / 1) + wid * 128;
            v0 = seg[      lane];
            v1 = seg[ 32 + lane];
            v2 = seg[ 64 + lane];
            v3 = seg[ 96 + lane];
        }

        // warp-private transpose: write step 32j+l, read steps 4l..4l+3
        float* s = sb[wid][r & 1];
        s[      lane] = b0;
        s[ 32 + lane] = b1;
        s[ 64 + lane] = b2;
        s[ 96 + lane] = b3;
        __syncwarp();
        const float4 bb = *(const float4*)(s + 4 * lane);

        // local fold of 4 consecutive steps: loc = a^3*b0 + a^2*b1 + a*b2 + b3
        const float loc = fmaf(a, fmaf(a, fmaf(a, bb.x, bb.y), bb.z), bb.w);
        const float h = loc * ainv4l;

        // ONE inclusive warp scan over lane aggregates
        float p = h;
        #pragma unroll
        for (int off = 1; off < 32; off <<= 1) {
            float n = __shfl_up_sync(0xffffffffu, p, off);
            if (lane >= off) p += n;
        }

        // publish warp total: S_w = p at lane 31 (warp sum, a^{124}-scaled)
        if (lane == 31) warpS[r & 1][wid] = p;
        __syncthreads();

        // serial 8-term carry combine, computed redundantly by all threads:
        //   T_{w} entering warp w;  t_next = fold of all 8 warps
        float tn = t, T = t;
        #pragma unroll
        for (int w = 0; w < WARPS; w++) {
            if (w == wid) T = tn;
            tn = fmaf(a128, tn, a124 * warpS[r & 1][w]);
        }
        t = tn;   // carry into next round

        // entering carry for this lane's 4-step block, then emit 4 outputs
        const float Tl = fmaf(ap4l, T, ap4lm4 * (p - h));
        const float o0 = fmaf(a, Tl, bb.x);
        const float o1 = fmaf(a, o0, bb.y);
        const float o2 = fmaf(a, o1, bb.z);
        const float o3 = fmaf(a, o2, bb.w);
        orow4[r * (RSTEPS / 4) + wid * 32 + lane] = make_float4(o0, o1, o2, o3);
    }
}

extern "C" void kernel_launch(void* const* d_in, const int* in_sizes, int n_in,
                              void* d_out, int out_size)
{
    (void)in_sizes; (void)n_in; (void)out_size;
    const float4* in = (const float4*)d_in[0];
    const float*  rR = (const float*)d_in[1];
    const float*  rC = (const float*)d_in[2];
    const float*  rA = (const float*)d_in[3];
    const float*  rG = (const float*)d_in[4];
    float* out = (float*)d_out;

    // one block per row: 8192 blocks of 256 threads (8 warps)
    dim3 grid(NROWS);
    dim3 block(BLOCK);
    rc_scan_kernel<<<grid, block>>>(in, rR, rC, rA, rG, out);
}

// round 17
// speedup vs baseline: 6.5656x; 6.5656x over previous
#include <cuda_runtime.h>
#include <math.h>

// Problem constants (fixed by the reference's setup_inputs)
#define NROWS   8192          // B
#define SLEN    4096          // S
#define NCHUNK  (SLEN / 32)   // 128 warp-iterations per row
#define PF      8             // prefetch depth (chunks in flight per warp)
#define BLOCK   128           // 4 warps/block

#define DELTA_T 900.0
// COOLING_SIGN = -1.0

__device__ __forceinline__ double bounded_d(double raw, double lo, double hi) {
    double s = 1.0 / (1.0 + exp(-raw));
    return lo + (hi - lo) * s;
}

// One warp per batch row (R7 winner body). t' = a*t + b_s with constant a;
// 32 steps resolved per iteration with a warp prefix-sum:
//   t_{lane} = a^{lane} * ( a * t_carry + sum_{j<=lane} a^{-j} * b_j )
// R16 lessons: independent warps + deep private ring is the only structure
// that improves this workload. This version extends the one proven lever:
//   - PF=8: double per-warp outstanding coalesced 512B loads
//   - __ldcs / __stcs: zero-reuse streams -> L1-bypass + L2 evict-first
__global__ __launch_bounds__(BLOCK)
void rc_scan_kernel(const float4* __restrict__ in,
                    const float*  __restrict__ pR,
                    const float*  __restrict__ pC,
                    const float*  __restrict__ pA,
                    const float*  __restrict__ pG,
                    float*        __restrict__ out)
{
    const int gwarp = (blockIdx.x * BLOCK + threadIdx.x) >> 5;
    const int lane  = threadIdx.x & 31;
    if (gwarp >= NROWS) return;

    // --- scalar parameters (sigmoid-bounded), computed in double, negligible ---
    const double R = bounded_d((double)*pR, 1e-4, 0.2);
    const double C = bounded_d((double)*pC, 1e5, 1e8);
    const double A = bounded_d((double)*pA, 0.0, 0.2);
    const double G = bounded_d((double)*pG, 1.0, 20000.0);

    const double dtC = DELTA_T / C;
    const double a_d = 1.0 - dtC / R;       // ~0.9633 for given inputs
    const float  a   = (float)a_d;
    const float  kTo = (float)(dtC / R);    // coeff of t_out
    const float  kU  = (float)(-G * dtC);   // COOLING_SIGN * g * dt/C
    const float  kSo = (float)(A * dtC);    // coeff of solar

    const double la   = log(a_d);
    const float  apow = (float)exp(la * (double)lane);    // a^lane   (<=1)
    const float  ainv = (float)exp(-la * (double)lane);   // a^-lane  (<=~3.2)

    const float4* row  = in  + (size_t)gwarp * SLEN;  // 4 floats/step == one float4
    float*        orow = out + (size_t)gwarp * SLEN;

    // t_prev initial carry = t_in[b, 0] (channel 0 of step 0); broadcast load
    float t = __ldg((const float*)row);

    // Prime the 8-deep ring buffer: 8 independent coalesced loads in flight.
    float4 v[PF];
    #pragma unroll
    for (int k = 0; k < PF; k++)
        v[k] = __ldcs(row + k * 32 + lane);

    #pragma unroll 8
    for (int ch = 0; ch < NCHUNK; ch++) {
        // consume the oldest buffered chunk
        const float4 cur = v[ch & (PF - 1)];

        // refill that slot with chunk ch+PF (issued before the shfl chain,
        // so it overlaps the serial prefix + next PF-1 iterations)
        if (ch + PF < NCHUNK)
            v[ch & (PF - 1)] = __ldcs(row + (ch + PF) * 32 + lane);

        // b_s = kTo*t_out + kU*u + kSo*solar ; rescale for the prefix
        float b = fmaf(kTo, cur.y, fmaf(kU, cur.z, kSo * cur.w));
        float c = b * ainv;

        // inclusive warp prefix sum of c
        #pragma unroll
        for (int off = 1; off < 32; off <<= 1) {
            float n = __shfl_up_sync(0xffffffffu, c, off);
            if (lane >= off) c += n;
        }

        // t_lane = a^lane * (a * t_carry + prefix)
        float tv = apow * fmaf(a, t, c);
        __stcs(orow + ch * 32 + lane, tv);

        // carry out of this chunk = lane 31's value
        t = __shfl_sync(0xffffffffu, tv, 31);
    }
}

extern "C" void kernel_launch(void* const* d_in, const int* in_sizes, int n_in,
                              void* d_out, int out_size)
{
    (void)in_sizes; (void)n_in; (void)out_size;
    const float4* in = (const float4*)d_in[0];
    const float*  rR = (const float*)d_in[1];
    const float*  rC = (const float*)d_in[2];
    const float*  rA = (const float*)d_in[3];
    const float*  rG = (const float*)d_in[4];
    float* out = (float*)d_out;

    // one warp per row: 8192 warps, 4 warps (128 threads) per block
    dim3 grid(NROWS / (BLOCK / 32));
    dim3 block(BLOCK);
    rc_scan_kernel<<<grid, block>>>(in, rR, rC, rA, rG, out);
}